// round 1
// baseline (speedup 1.0000x reference)
#include <cuda_runtime.h>
#include <cstdint>

// Problem dims
#define NBAGS 512
#define MSENT 8
#define TLEN  64
#define IND   360
#define HD    230
#define G3    690      // 3*HD
#define H2    460      // 2*HD
#define OUTD  53
#define BALL  4096     // NBAGS*MSENT
#define ROWSALL 262144 // BALL*TLEN

// ---------------- scratch (static device globals; allocation-free) ----------------
__device__ float g_xg_f[(size_t)ROWSALL * G3];  // input gates, forward  (~689 MB)
__device__ float g_xg_r[(size_t)ROWSALL * G3];  // input gates, reverse  (~689 MB)
__device__ float g_hcat[(size_t)ROWSALL * H2];  // [b][t][hf|hr]         (~460 MB)
__device__ float g_sw[ROWSALL];                 // word scores
__device__ float g_wv[(size_t)BALL * H2];       // word vectors
__device__ float g_ss[BALL];                    // sentence scores
__device__ float g_sv[(size_t)NBAGS * H2];      // sentence vectors

// =====================================================================
// K1: input projection  C[bt][g] = sum_i bag[bt][i]*W_ih[g][i] + b_ih[g]
// BM=128, BN=64, BK=8, 256 thr, 8x4 microkernel. grid.z = dir.
// =====================================================================
__global__ void __launch_bounds__(256) k_proj(const float* __restrict__ bag,
        const float* __restrict__ Wf, const float* __restrict__ bf,
        const float* __restrict__ Wr, const float* __restrict__ br)
{
    __shared__ float As[8][128];
    __shared__ float Bs[8][64];
    const int dir = blockIdx.z;
    const float* W    = dir ? Wr : Wf;
    const float* bias = dir ? br : bf;
    float* C = dir ? g_xg_r : g_xg_f;

    const int m0 = blockIdx.y * 128;
    const int g0 = blockIdx.x * 64;
    const int tid = threadIdx.x;
    const int tx = tid & 15;   // N: 16 x 4 = 64
    const int ty = tid >> 4;   // M: 16 x 8 = 128

    float acc[8][4] = {};

    const int arow = tid >> 1;
    const int ak   = (tid & 1) * 4;
    const int bidx = tid * 2;
    const int bg   = bidx >> 3;
    const int bk   = bidx & 7;

    for (int k0 = 0; k0 < IND; k0 += 8) {
        float4 av = *(const float4*)(bag + (size_t)(m0 + arow) * IND + k0 + ak);
        float2 bv = make_float2(0.f, 0.f);
        int gg = g0 + bg;
        if (gg < G3) bv = *(const float2*)(W + (size_t)gg * IND + k0 + bk);
        __syncthreads();
        As[ak + 0][arow] = av.x; As[ak + 1][arow] = av.y;
        As[ak + 2][arow] = av.z; As[ak + 3][arow] = av.w;
        Bs[bk + 0][bg] = bv.x;   Bs[bk + 1][bg] = bv.y;
        __syncthreads();
        #pragma unroll
        for (int k = 0; k < 8; k++) {
            float a[8], b4[4];
            *(float4*)(a)     = *(const float4*)&As[k][ty * 8];
            *(float4*)(a + 4) = *(const float4*)&As[k][ty * 8 + 4];
            *(float4*)(b4)    = *(const float4*)&Bs[k][tx * 4];
            #pragma unroll
            for (int i = 0; i < 8; i++)
                #pragma unroll
                for (int j = 0; j < 4; j++)
                    acc[i][j] += a[i] * b4[j];
        }
    }
    #pragma unroll
    for (int i = 0; i < 8; i++) {
        size_t row = (size_t)m0 + ty * 8 + i;
        #pragma unroll
        for (int j = 0; j < 4; j++) {
            int g = g0 + tx * 4 + j;
            if (g < G3) C[row * G3 + g] = acc[i][j] + bias[g];
        }
    }
}

// =====================================================================
// K2: GRU. One CTA owns 32 batch rows for one direction; full T loop
// with h resident in smem. Per step: hg = h @ W_hh^T (+b_hh) computed in
// 11 g-tiles of 64 with W staged to smem, then elementwise gates.
// smem: h_s[32][231] + ws[64][231] + hg[32][690] = 177,024 B
// =====================================================================
__global__ void __launch_bounds__(256) k_gru(const float* __restrict__ Whhf,
        const float* __restrict__ bhhf, const float* __restrict__ Whhr,
        const float* __restrict__ bhhr)
{
    extern __shared__ float sm[];
    float* h_s = sm;                       // 32*231
    float* ws  = sm + 32 * 231;            // 64*231
    float* hg  = sm + 32 * 231 + 64 * 231; // 32*690

    const int bx  = blockIdx.x;
    const int dir = bx >> 7;          // 128 CTAs per dir
    const int rb  = (bx & 127) * 32;
    const float* Whh = dir ? Whhr : Whhf;
    const float* bhh = dir ? bhhr : bhhf;
    const float* xg  = dir ? g_xg_r : g_xg_f;

    const int tid = threadIdx.x;
    const int gx = tid & 63;
    const int ry = tid >> 6;

    for (int i = tid; i < 32 * 231; i += 256) h_s[i] = 0.f;
    __syncthreads();

    for (int ti = 0; ti < TLEN; ti++) {
        const int t = dir ? (TLEN - 1 - ti) : ti;
        // hg = h @ Whh^T + bhh, tiled over g
        for (int tile = 0; tile < 11; tile++) {
            const int g0 = tile * 64;
            __syncthreads();   // prev compute & gate done before ws overwrite
            for (int idx = tid; idx < 64 * HD; idx += 256) {
                int gg = idx / HD;
                int kk = idx - gg * HD;
                int g = g0 + gg;
                ws[gg * 231 + kk] = (g < G3) ? Whh[(size_t)g * HD + kk] : 0.f;
            }
            __syncthreads();
            const int g = g0 + gx;
            float acc[8] = {};
            #pragma unroll 2
            for (int k = 0; k < HD; k++) {
                float w = ws[gx * 231 + k];
                #pragma unroll
                for (int i = 0; i < 8; i++)
                    acc[i] += w * h_s[(ry * 8 + i) * 231 + k];
            }
            if (g < G3) {
                float bb = bhh[g];
                #pragma unroll
                for (int i = 0; i < 8; i++)
                    hg[(ry * 8 + i) * G3 + g] = acc[i] + bb;
            }
        }
        __syncthreads();
        // gates + state update + output
        for (int e = tid; e < 32 * HD; e += 256) {
            int r_ = e / HD;
            int j  = e - r_ * HD;
            size_t xb = ((size_t)(rb + r_) * TLEN + t) * G3;
            float xr = xg[xb + j];
            float xz = xg[xb + HD + j];
            float xn = xg[xb + 2 * HD + j];
            float hgr = hg[r_ * G3 + j];
            float hgz = hg[r_ * G3 + HD + j];
            float hgn = hg[r_ * G3 + 2 * HD + j];
            float rr = 1.f / (1.f + __expf(-(xr + hgr)));
            float zz = 1.f / (1.f + __expf(-(xz + hgz)));
            float nn = tanhf(xn + rr * hgn);
            float hold = h_s[r_ * 231 + j];
            float hn = (1.f - zz) * nn + zz * hold;
            h_s[r_ * 231 + j] = hn;
            g_hcat[((size_t)(rb + r_) * TLEN + t) * H2 + dir * HD + j] = hn;
        }
    }
}

// =====================================================================
// K3: attention score  s[row] = p . tanh(X[row] @ W + b)
// 32 rows/CTA, W staged in 460x64 smem tiles. Deterministic tree reduce.
// smem: xs[32*460] + Wt[460*65] + red[64*32] = 186,672 B
// =====================================================================
__global__ void __launch_bounds__(256) k_score(const float* __restrict__ X,
        const float* __restrict__ W, const float* __restrict__ b,
        const float* __restrict__ p, float* __restrict__ s)
{
    extern __shared__ float sm[];
    float* xs  = sm;                 // 32*460
    float* Wt  = sm + 32 * H2;       // 460*65
    float* red = Wt + H2 * 65;       // 64*32

    const int r0 = blockIdx.x * 32;
    const int tid = threadIdx.x;
    const int jx = tid & 63;
    const int ry = tid >> 6;

    for (int idx = tid; idx < 32 * H2; idx += 256)
        xs[idx] = X[(size_t)r0 * H2 + idx];

    float sacc[8] = {};
    for (int j0 = 0; j0 < H2; j0 += 64) {
        __syncthreads();
        for (int idx = tid; idx < H2 * 64; idx += 256) {
            int i  = idx >> 6;
            int jj = idx & 63;
            int j = j0 + jj;
            Wt[i * 65 + jj] = (j < H2) ? W[(size_t)i * H2 + j] : 0.f;
        }
        __syncthreads();
        int j = j0 + jx;
        if (j < H2) {
            float facc[8] = {};
            for (int i = 0; i < H2; i++) {
                float w = Wt[i * 65 + jx];
                #pragma unroll
                for (int r = 0; r < 8; r++)
                    facc[r] += w * xs[(ry * 8 + r) * H2 + i];
            }
            float pj = p[j], bj = b[j];
            #pragma unroll
            for (int r = 0; r < 8; r++)
                sacc[r] += pj * tanhf(facc[r] + bj);
        }
    }
    __syncthreads();
    #pragma unroll
    for (int r = 0; r < 8; r++)
        red[jx * 32 + ry * 8 + r] = sacc[r];
    __syncthreads();
    if (tid < 32) {
        float v = 0.f;
        for (int q = 0; q < 64; q++) v += red[q * 32 + tid];
        s[r0 + tid] = v;
    }
}

// =====================================================================
// K4: softmax over L within a group + weighted sum -> V[group][460]
// =====================================================================
__global__ void k_attnsum(const float* __restrict__ s, const float* __restrict__ X,
                          float* __restrict__ V, int L)
{
    __shared__ float sv[64];
    __shared__ float alpha[64];
    const int b = blockIdx.x;
    const int tid = threadIdx.x;
    if (tid < L) sv[tid] = s[b * L + tid];
    __syncthreads();
    float m = -1e30f;
    for (int l = 0; l < L; l++) m = fmaxf(m, sv[l]);
    float den = 0.f;
    for (int l = 0; l < L; l++) den += __expf(sv[l] - m);
    if (tid < L) alpha[tid] = __expf(sv[tid] - m) / den;
    __syncthreads();
    for (int j = tid; j < H2; j += blockDim.x) {
        float acc = 0.f;
        for (int l = 0; l < L; l++)
            acc += alpha[l] * X[((size_t)b * L + l) * H2 + j];
        V[(size_t)b * H2 + j] = acc;
    }
}

// =====================================================================
// K5: FC on sentence vectors + scatter into (DOCS,ENT,ENT,OUT)
// =====================================================================
__global__ void k_fc_scatter(const float* __restrict__ fcW, const float* __restrict__ fcb,
                             const int* __restrict__ pairs, float* __restrict__ out)
{
    __shared__ float sv[H2];
    const int r = blockIdx.x;
    const int tid = threadIdx.x;
    for (int j = tid; j < H2; j += blockDim.x) sv[j] = g_sv[(size_t)r * H2 + j];
    __syncthreads();
    if (tid < OUTD) {
        float acc = fcb[tid];
        for (int j = 0; j < H2; j++) acc += sv[j] * fcW[(size_t)tid * H2 + j];
        int p0 = pairs[r * 3], p1 = pairs[r * 3 + 1], p2 = pairs[r * 3 + 2];
        out[((size_t)(p0 * 64 + p1 * 8 + p2)) * OUTD + tid] = acc;
    }
}

__global__ void k_zero(float* __restrict__ out, int n)
{
    int i = blockIdx.x * blockDim.x + threadIdx.x;
    if (i < n) out[i] = 0.f;
}

// =====================================================================
extern "C" void kernel_launch(void* const* d_in, const int* in_sizes, int n_in,
                              void* d_out, int out_size)
{
    const float* bag   = (const float*)d_in[0];
    const float* Wihf  = (const float*)d_in[1];
    const float* Whhf  = (const float*)d_in[2];
    const float* bihf  = (const float*)d_in[3];
    const float* bhhf  = (const float*)d_in[4];
    const float* Wihr  = (const float*)d_in[5];
    const float* Whhr  = (const float*)d_in[6];
    const float* bihr  = (const float*)d_in[7];
    const float* bhhr  = (const float*)d_in[8];
    const float* Wword = (const float*)d_in[9];
    const float* bword = (const float*)d_in[10];
    const float* pword = (const float*)d_in[11];
    const float* Wsent = (const float*)d_in[12];
    const float* bsent = (const float*)d_in[13];
    const float* psent = (const float*)d_in[14];
    const float* fcW   = (const float*)d_in[15];
    const float* fcb   = (const float*)d_in[16];
    const int*   pairs = (const int*)d_in[17];
    float* out = (float*)d_out;

    // device-symbol addresses for the reusable kernels
    void *p_hcat, *p_sw, *p_wv, *p_ss, *p_sv;
    cudaGetSymbolAddress(&p_hcat, g_hcat);
    cudaGetSymbolAddress(&p_sw,   g_sw);
    cudaGetSymbolAddress(&p_wv,   g_wv);
    cudaGetSymbolAddress(&p_ss,   g_ss);
    cudaGetSymbolAddress(&p_sv,   g_sv);

    const size_t smem_gru   = (size_t)(32 * 231 + 64 * 231 + 32 * 690) * sizeof(float); // 177,024
    const size_t smem_score = (size_t)(32 * H2 + H2 * 65 + 64 * 32) * sizeof(float);    // 186,672
    cudaFuncSetAttribute(k_gru,   cudaFuncAttributeMaxDynamicSharedMemorySize, (int)smem_gru);
    cudaFuncSetAttribute(k_score, cudaFuncAttributeMaxDynamicSharedMemorySize, (int)smem_score);

    // 1) zero output (poisoned by harness)
    k_zero<<<(out_size + 255) / 256, 256>>>(out, out_size);

    // 2) input projections for both directions
    dim3 gproj((G3 + 63) / 64, ROWSALL / 128, 2);
    k_proj<<<gproj, 256>>>(bag, Wihf, bihf, Wihr, bihr);

    // 3) bidirectional GRU (128 CTAs per dir)
    k_gru<<<256, 256, smem_gru>>>(Whhf, bhhf, Whhr, bhhr);

    // 4) word attention
    k_score<<<ROWSALL / 32, 256, smem_score>>>((const float*)p_hcat, Wword, bword, pword, (float*)p_sw);
    k_attnsum<<<BALL, 256>>>((const float*)p_sw, (const float*)p_hcat, (float*)p_wv, TLEN);

    // 5) sentence attention
    k_score<<<BALL / 32, 256, smem_score>>>((const float*)p_wv, Wsent, bsent, psent, (float*)p_ss);
    k_attnsum<<<NBAGS, 256>>>((const float*)p_ss, (const float*)p_wv, (float*)p_sv, MSENT);

    // 6) FC + scatter
    k_fc_scatter<<<NBAGS, 64>>>(fcW, fcb, pairs, out);
}

// round 3
// speedup vs baseline: 1.0038x; 1.0038x over previous
#include <cuda_runtime.h>
#include <cstdint>

// Problem dims
#define NBAGS 512
#define MSENT 8
#define TLEN  64
#define IND   360
#define HD    230
#define G3    690      // 3*HD
#define H2    460      // 2*HD
#define OUTD  53
#define BALL  4096     // NBAGS*MSENT
#define ROWSALL 262144 // BALL*TLEN

// ---------------- scratch (static device globals; allocation-free) ----------------
__device__ float g_xg_f[(size_t)ROWSALL * G3];  // input gates, forward  (~689 MB)
__device__ float g_xg_r[(size_t)ROWSALL * G3];  // input gates, reverse  (~689 MB)
__device__ float g_hcat[(size_t)ROWSALL * H2];  // [b][t][hf|hr]         (~460 MB)
__device__ float g_sw[ROWSALL];                 // word scores
__device__ float g_wv[(size_t)BALL * H2];       // word vectors
__device__ float g_ss[BALL];                    // sentence scores
__device__ float g_sv[(size_t)NBAGS * H2];      // sentence vectors

// =====================================================================
// K1: input projection  C[bt][g] = sum_i bag[bt][i]*W_ih[g][i] + b_ih[g]
// BM=128, BN=64, BK=8, 256 thr, 8x4 microkernel. grid.z = dir.
// =====================================================================
__global__ void __launch_bounds__(256) k_proj(const float* __restrict__ bag,
        const float* __restrict__ Wf, const float* __restrict__ bf,
        const float* __restrict__ Wr, const float* __restrict__ br)
{
    __shared__ float As[8][128];
    __shared__ float Bs[8][64];
    const int dir = blockIdx.z;
    const float* W    = dir ? Wr : Wf;
    const float* bias = dir ? br : bf;
    float* C = dir ? g_xg_r : g_xg_f;

    const int m0 = blockIdx.y * 128;
    const int g0 = blockIdx.x * 64;
    const int tid = threadIdx.x;
    const int tx = tid & 15;   // N: 16 x 4 = 64
    const int ty = tid >> 4;   // M: 16 x 8 = 128

    float acc[8][4] = {};

    const int arow = tid >> 1;
    const int ak   = (tid & 1) * 4;
    const int bidx = tid * 2;
    const int bg   = bidx >> 3;
    const int bk   = bidx & 7;

    for (int k0 = 0; k0 < IND; k0 += 8) {
        float4 av = *(const float4*)(bag + (size_t)(m0 + arow) * IND + k0 + ak);
        float2 bv = make_float2(0.f, 0.f);
        int gg = g0 + bg;
        if (gg < G3) bv = *(const float2*)(W + (size_t)gg * IND + k0 + bk);
        __syncthreads();
        As[ak + 0][arow] = av.x; As[ak + 1][arow] = av.y;
        As[ak + 2][arow] = av.z; As[ak + 3][arow] = av.w;
        Bs[bk + 0][bg] = bv.x;   Bs[bk + 1][bg] = bv.y;
        __syncthreads();
        #pragma unroll
        for (int k = 0; k < 8; k++) {
            float a[8], b4[4];
            *(float4*)(a)     = *(const float4*)&As[k][ty * 8];
            *(float4*)(a + 4) = *(const float4*)&As[k][ty * 8 + 4];
            *(float4*)(b4)    = *(const float4*)&Bs[k][tx * 4];
            #pragma unroll
            for (int i = 0; i < 8; i++)
                #pragma unroll
                for (int j = 0; j < 4; j++)
                    acc[i][j] += a[i] * b4[j];
        }
    }
    #pragma unroll
    for (int i = 0; i < 8; i++) {
        size_t row = (size_t)m0 + ty * 8 + i;
        #pragma unroll
        for (int j = 0; j < 4; j++) {
            int g = g0 + tx * 4 + j;
            if (g < G3) C[row * G3 + g] = acc[i][j] + bias[g];
        }
    }
}

// =====================================================================
// K2: GRU. One CTA owns 32 batch rows for one direction; full T loop
// with h resident in smem. Per step: hg = h @ W_hh^T (+b_hh) computed in
// 11 g-tiles of 64 with W staged to smem, then elementwise gates.
// smem: h_s[32][231] + ws[64][231] + hg[32][690] = 177,024 B
// =====================================================================
__global__ void __launch_bounds__(256) k_gru(const float* __restrict__ Whhf,
        const float* __restrict__ bhhf, const float* __restrict__ Whhr,
        const float* __restrict__ bhhr)
{
    extern __shared__ float sm[];
    float* h_s = sm;                       // 32*231
    float* ws  = sm + 32 * 231;            // 64*231
    float* hg  = sm + 32 * 231 + 64 * 231; // 32*690

    const int bx  = blockIdx.x;
    const int dir = bx >> 7;          // 128 CTAs per dir
    const int rb  = (bx & 127) * 32;
    const float* Whh = dir ? Whhr : Whhf;
    const float* bhh = dir ? bhhr : bhhf;
    const float* xg  = dir ? g_xg_r : g_xg_f;

    const int tid = threadIdx.x;
    const int gx = tid & 63;
    const int ry = tid >> 6;

    for (int i = tid; i < 32 * 231; i += 256) h_s[i] = 0.f;
    __syncthreads();

    for (int ti = 0; ti < TLEN; ti++) {
        const int t = dir ? (TLEN - 1 - ti) : ti;
        // hg = h @ Whh^T + bhh, tiled over g
        for (int tile = 0; tile < 11; tile++) {
            const int g0 = tile * 64;
            __syncthreads();   // prev compute & gate done before ws overwrite
            for (int idx = tid; idx < 64 * HD; idx += 256) {
                int gg = idx / HD;
                int kk = idx - gg * HD;
                int g = g0 + gg;
                ws[gg * 231 + kk] = (g < G3) ? Whh[(size_t)g * HD + kk] : 0.f;
            }
            __syncthreads();
            const int g = g0 + gx;
            float acc[8] = {};
            #pragma unroll 2
            for (int k = 0; k < HD; k++) {
                float w = ws[gx * 231 + k];
                #pragma unroll
                for (int i = 0; i < 8; i++)
                    acc[i] += w * h_s[(ry * 8 + i) * 231 + k];
            }
            if (g < G3) {
                float bb = bhh[g];
                #pragma unroll
                for (int i = 0; i < 8; i++)
                    hg[(ry * 8 + i) * G3 + g] = acc[i] + bb;
            }
        }
        __syncthreads();
        // gates + state update + output
        for (int e = tid; e < 32 * HD; e += 256) {
            int r_ = e / HD;
            int j  = e - r_ * HD;
            size_t xb = ((size_t)(rb + r_) * TLEN + t) * G3;
            float xr = xg[xb + j];
            float xz = xg[xb + HD + j];
            float xn = xg[xb + 2 * HD + j];
            float hgr = hg[r_ * G3 + j];
            float hgz = hg[r_ * G3 + HD + j];
            float hgn = hg[r_ * G3 + 2 * HD + j];
            float rr = 1.f / (1.f + __expf(-(xr + hgr)));
            float zz = 1.f / (1.f + __expf(-(xz + hgz)));
            float nn = tanhf(xn + rr * hgn);
            float hold = h_s[r_ * 231 + j];
            float hn = (1.f - zz) * nn + zz * hold;
            h_s[r_ * 231 + j] = hn;
            g_hcat[((size_t)(rb + r_) * TLEN + t) * H2 + dir * HD + j] = hn;
        }
    }
}

// =====================================================================
// K3: attention score  s[row] = p . tanh(X[row] @ W + b)
// 32 rows/CTA, W staged in 460x64 smem tiles. Deterministic tree reduce.
// smem: xs[32*460] + Wt[460*65] + red[64*32] = 186,672 B
// =====================================================================
__global__ void __launch_bounds__(256) k_score(const float* __restrict__ X,
        const float* __restrict__ W, const float* __restrict__ b,
        const float* __restrict__ p, float* __restrict__ s)
{
    extern __shared__ float sm[];
    float* xs  = sm;                 // 32*460
    float* Wt  = sm + 32 * H2;       // 460*65
    float* red = Wt + H2 * 65;       // 64*32

    const int r0 = blockIdx.x * 32;
    const int tid = threadIdx.x;
    const int jx = tid & 63;
    const int ry = tid >> 6;

    for (int idx = tid; idx < 32 * H2; idx += 256)
        xs[idx] = X[(size_t)r0 * H2 + idx];

    float sacc[8] = {};
    for (int j0 = 0; j0 < H2; j0 += 64) {
        __syncthreads();
        for (int idx = tid; idx < H2 * 64; idx += 256) {
            int i  = idx >> 6;
            int jj = idx & 63;
            int j = j0 + jj;
            Wt[i * 65 + jj] = (j < H2) ? W[(size_t)i * H2 + j] : 0.f;
        }
        __syncthreads();
        int j = j0 + jx;
        if (j < H2) {
            float facc[8] = {};
            for (int i = 0; i < H2; i++) {
                float w = Wt[i * 65 + jx];
                #pragma unroll
                for (int r = 0; r < 8; r++)
                    facc[r] += w * xs[(ry * 8 + r) * H2 + i];
            }
            float pj = p[j], bj = b[j];
            #pragma unroll
            for (int r = 0; r < 8; r++)
                sacc[r] += pj * tanhf(facc[r] + bj);
        }
    }
    __syncthreads();
    #pragma unroll
    for (int r = 0; r < 8; r++)
        red[jx * 32 + ry * 8 + r] = sacc[r];
    __syncthreads();
    if (tid < 32) {
        float v = 0.f;
        for (int q = 0; q < 64; q++) v += red[q * 32 + tid];
        s[r0 + tid] = v;
    }
}

// =====================================================================
// K4: softmax over L within a group + weighted sum -> V[group][460]
// =====================================================================
__global__ void k_attnsum(const float* __restrict__ s, const float* __restrict__ X,
                          float* __restrict__ V, int L)
{
    __shared__ float sv[64];
    __shared__ float alpha[64];
    const int b = blockIdx.x;
    const int tid = threadIdx.x;
    if (tid < L) sv[tid] = s[b * L + tid];
    __syncthreads();
    float m = -1e30f;
    for (int l = 0; l < L; l++) m = fmaxf(m, sv[l]);
    float den = 0.f;
    for (int l = 0; l < L; l++) den += __expf(sv[l] - m);
    if (tid < L) alpha[tid] = __expf(sv[tid] - m) / den;
    __syncthreads();
    for (int j = tid; j < H2; j += blockDim.x) {
        float acc = 0.f;
        for (int l = 0; l < L; l++)
            acc += alpha[l] * X[((size_t)b * L + l) * H2 + j];
        V[(size_t)b * H2 + j] = acc;
    }
}

// =====================================================================
// K5: FC on sentence vectors + scatter into (DOCS,ENT,ENT,OUT)
// =====================================================================
__global__ void k_fc_scatter(const float* __restrict__ fcW, const float* __restrict__ fcb,
                             const int* __restrict__ pairs, float* __restrict__ out)
{
    __shared__ float sv[H2];
    const int r = blockIdx.x;
    const int tid = threadIdx.x;
    for (int j = tid; j < H2; j += blockDim.x) sv[j] = g_sv[(size_t)r * H2 + j];
    __syncthreads();
    if (tid < OUTD) {
        float acc = fcb[tid];
        for (int j = 0; j < H2; j++) acc += sv[j] * fcW[(size_t)tid * H2 + j];
        int p0 = pairs[r * 3], p1 = pairs[r * 3 + 1], p2 = pairs[r * 3 + 2];
        out[((size_t)(p0 * 64 + p1 * 8 + p2)) * OUTD + tid] = acc;
    }
}

__global__ void k_zero(float* __restrict__ out, int n)
{
    int i = blockIdx.x * blockDim.x + threadIdx.x;
    if (i < n) out[i] = 0.f;
}

// =====================================================================
extern "C" void kernel_launch(void* const* d_in, const int* in_sizes, int n_in,
                              void* d_out, int out_size)
{
    const float* bag   = (const float*)d_in[0];
    const float* Wihf  = (const float*)d_in[1];
    const float* Whhf  = (const float*)d_in[2];
    const float* bihf  = (const float*)d_in[3];
    const float* bhhf  = (const float*)d_in[4];
    const float* Wihr  = (const float*)d_in[5];
    const float* Whhr  = (const float*)d_in[6];
    const float* bihr  = (const float*)d_in[7];
    const float* bhhr  = (const float*)d_in[8];
    const float* Wword = (const float*)d_in[9];
    const float* bword = (const float*)d_in[10];
    const float* pword = (const float*)d_in[11];
    const float* Wsent = (const float*)d_in[12];
    const float* bsent = (const float*)d_in[13];
    const float* psent = (const float*)d_in[14];
    const float* fcW   = (const float*)d_in[15];
    const float* fcb   = (const float*)d_in[16];
    const int*   pairs = (const int*)d_in[17];
    float* out = (float*)d_out;

    // device-symbol addresses for the reusable kernels
    void *p_hcat, *p_sw, *p_wv, *p_ss, *p_sv;
    cudaGetSymbolAddress(&p_hcat, g_hcat);
    cudaGetSymbolAddress(&p_sw,   g_sw);
    cudaGetSymbolAddress(&p_wv,   g_wv);
    cudaGetSymbolAddress(&p_ss,   g_ss);
    cudaGetSymbolAddress(&p_sv,   g_sv);

    const size_t smem_gru   = (size_t)(32 * 231 + 64 * 231 + 32 * 690) * sizeof(float); // 177,024
    const size_t smem_score = (size_t)(32 * H2 + H2 * 65 + 64 * 32) * sizeof(float);    // 186,672
    cudaFuncSetAttribute(k_gru,   cudaFuncAttributeMaxDynamicSharedMemorySize, (int)smem_gru);
    cudaFuncSetAttribute(k_score, cudaFuncAttributeMaxDynamicSharedMemorySize, (int)smem_score);

    // 1) zero output (poisoned by harness)
    k_zero<<<(out_size + 255) / 256, 256>>>(out, out_size);

    // 2) input projections for both directions
    dim3 gproj((G3 + 63) / 64, ROWSALL / 128, 2);
    k_proj<<<gproj, 256>>>(bag, Wihf, bihf, Wihr, bihr);

    // 3) bidirectional GRU (128 CTAs per dir)
    k_gru<<<256, 256, smem_gru>>>(Whhf, bhhf, Whhr, bhhr);

    // 4) word attention
    k_score<<<ROWSALL / 32, 256, smem_score>>>((const float*)p_hcat, Wword, bword, pword, (float*)p_sw);
    k_attnsum<<<BALL, 256>>>((const float*)p_sw, (const float*)p_hcat, (float*)p_wv, TLEN);

    // 5) sentence attention
    k_score<<<BALL / 32, 256, smem_score>>>((const float*)p_wv, Wsent, bsent, psent, (float*)p_ss);
    k_attnsum<<<NBAGS, 256>>>((const float*)p_ss, (const float*)p_wv, (float*)p_sv, MSENT);

    // 6) FC + scatter
    k_fc_scatter<<<NBAGS, 64>>>(fcW, fcb, pairs, out);
}